// round 4
// baseline (speedup 1.0000x reference)
#include <cuda_runtime.h>

// ---------------------------------------------------------------------------
// WeightedTP: tp[n,w] = sum_k sum_{j} h[n,k] * c[n,j] * Wsym[k,j,w]
// j = symmetrized uv-pairs (u<=v), 272 = 2 paths x 136. Bias as k=64, h=1.
// R3: tp_kernel with 4 rows/thread (16 MAC per W-load), broadcast LDS.128 of
// non-duplicated c, 8 k-splits (512 CTAs), transposed g_cT/g_hT for coalesced
// smem fill. out_kernel: 4 rows/block (512 blocks) + warp-reduce.
// ---------------------------------------------------------------------------

#define MAXN 2048
#define NK 65            // 64 hidden rows + 1 bias row
#define NJ 272           // 2 paths * 136 unordered pairs
#define NW 128
#define KSPLIT 8

#define PATH_COEFF 0.04419417382415922f   // 1/sqrt(512)
#define CG110      0.57735026918962576f   // 1/sqrt(3)
#define LN_EPS     1e-5f

typedef unsigned long long ull;

__device__ float g_hT[64 * MAXN];          // [k][n]
__device__ float g_cT[NJ * MAXN];          // [j][n]
__device__ float g_wsym[NK * NJ * NW];     // [k][j][w]
__device__ float g_tp[KSPLIT * MAXN * NW]; // k-split partials

// ---- packed f32x2 helpers (sm_103a) ----
__device__ __forceinline__ ull pack2(float x, float y) {
    ull r;
    asm("mov.b64 %0, {%1, %2};" : "=l"(r) : "f"(x), "f"(y));
    return r;
}
__device__ __forceinline__ void unpack2(ull v, float& x, float& y) {
    asm("mov.b64 {%0, %1}, %2;" : "=f"(x), "=f"(y) : "l"(v));
}
__device__ __forceinline__ ull ffma2(ull a, ull b, ull c) {
    ull d;
    asm("fma.rn.f32x2 %0, %1, %2, %3;" : "=l"(d) : "l"(a), "l"(b), "l"(c));
    return d;
}

__device__ __forceinline__ float silu_f(float v) {
    return v / (1.0f + __expf(-v));
}

// ---------------------------------------------------------------------------
// Kernel 1: build Wsym[k][jj][w]; jj = p*136 + tri(u,v), u<=v.
// ---------------------------------------------------------------------------
__global__ void repack_kernel(const float* __restrict__ w2,
                              const float* __restrict__ b2) {
    int idx = blockIdx.x * blockDim.x + threadIdx.x;
    const int total = NK * NJ * NW;
    if (idx >= total) return;
    int w    = idx & 127;
    int rest = idx >> 7;
    int jj   = rest % NJ;
    int k    = rest / NJ;
    int p = jj / 136;
    int q = jj % 136;
    int u = 0;
    while (q >= 16 - u) { q -= 16 - u; u++; }
    int v = u + q;
    const float* src = (k < 64) ? (w2 + (size_t)k * 65536) : b2;
    float val = src[((p * 256 + u * 16 + v) << 7) + w];
    if (u != v) val += src[((p * 256 + v * 16 + u) << 7) + w];
    g_wsym[idx] = val;
}

// ---------------------------------------------------------------------------
// Kernel 2: per-row prep — h (transposed), c (transposed).
// One warp per row, 8 rows per 256-thread block.
// ---------------------------------------------------------------------------
__global__ void prep_kernel(const float* __restrict__ x,
                            const float* __restrict__ lng,
                            const float* __restrict__ lnb,
                            const float* __restrict__ w1,
                            int N) {
    __shared__ float xs[8][64];
    __shared__ float lns[8][16];
    int warp = threadIdx.x >> 5;
    int lane = threadIdx.x & 31;
    int n = blockIdx.x * 8 + warp;
    if (n >= N) return;

    xs[warp][lane]      = x[(size_t)n * 64 + lane];
    xs[warp][lane + 32] = x[(size_t)n * 64 + 32 + lane];
    __syncwarp();

    // LayerNorm over the first 16 features
    float f = (lane < 16) ? xs[warp][lane] : 0.0f;
    float s = f;
    #pragma unroll
    for (int o = 16; o; o >>= 1) s += __shfl_xor_sync(0xffffffffu, s, o);
    float mu = s * (1.0f / 16.0f);
    float d = (lane < 16) ? (f - mu) : 0.0f;
    float ss = d * d;
    #pragma unroll
    for (int o = 16; o; o >>= 1) ss += __shfl_xor_sync(0xffffffffu, ss, o);
    float rstd = rsqrtf(ss * (1.0f / 16.0f) + LN_EPS);
    if (lane < 16) lns[warp][lane] = d * rstd * lng[lane] + lnb[lane];
    __syncwarp();

    // h = silu(ln @ w1), w1 is (16, 64); store transposed [k][n]
    #pragma unroll
    for (int t = 0; t < 2; t++) {
        int j = lane + 32 * t;
        float acc = 0.0f;
        #pragma unroll
        for (int i = 0; i < 16; i++) acc += lns[warp][i] * w1[i * 64 + j];
        g_hT[(size_t)j * MAXN + n] = silu_f(acc);
    }

    // c coefficients over unordered pairs (u<=v), PATH_COEFF folded; transposed [j][n]
    for (int t = lane; t < NJ; t += 32) {
        int p = t / 136;
        int q = t % 136;
        int u = 0;
        int qq = q;
        while (qq >= 16 - u) { qq -= 16 - u; u++; }
        int v = u + qq;
        float val;
        if (p == 0) {
            val = PATH_COEFF * xs[warp][u] * xs[warp][v];
        } else {
            const float* a = &xs[warp][16 + u * 3];
            const float* b = &xs[warp][16 + v * 3];
            val = PATH_COEFF * CG110 * (a[0] * b[0] + a[1] * b[1] + a[2] * b[2]);
        }
        g_cT[(size_t)t * MAXN + n] = val;
    }
}

// ---------------------------------------------------------------------------
// Kernel 3: main contraction. Grid (N/32, KSPLIT), 256 threads.
// Thread = (w-quad lw, 4 rows m0..m0+3). 16 MACs per 16B W-load.
// ---------------------------------------------------------------------------
__global__ __launch_bounds__(256) void tp_kernel(int N) {
    __shared__ float c_sm[NJ * 32];   // [j][m], non-duplicated
    __shared__ float h_sm[9 * 32];    // [kl][m]

    int tid   = threadIdx.x;
    int base  = blockIdx.x * 32;
    int split = blockIdx.y;
    int k0 = (split * NK) / KSPLIT;
    int k1 = ((split + 1) * NK) / KSPLIT;
    int kc = k1 - k0;

    for (int s = tid; s < NJ * 32; s += 256)
        c_sm[s] = g_cT[(size_t)(s >> 5) * MAXN + base + (s & 31)];
    for (int s = tid; s < kc * 32; s += 256) {
        int k = k0 + (s >> 5);
        h_sm[s] = (k == 64) ? 1.0f : g_hT[(size_t)k * MAXN + base + (s & 31)];
    }
    __syncthreads();

    int lw = tid & 31;
    int m0 = (tid >> 5) * 4;
    int mq = m0 >> 2;

    const longlong2* Wv = reinterpret_cast<const longlong2*>(g_wsym)
                          + (size_t)k0 * NJ * 32 + lw;
    const float4* c4p = reinterpret_cast<const float4*>(c_sm);

    ull acc[8];
    #pragma unroll
    for (int i = 0; i < 8; i++) acc[i] = 0;

    for (int k = k0; k < k1; k++) {
        ull p[8];
        #pragma unroll
        for (int i = 0; i < 8; i++) p[i] = 0;

        #pragma unroll 4
        for (int j = 0; j < NJ; j++) {
            longlong2 wv = Wv[(size_t)j * 32];
            float4 c4 = c4p[j * 8 + mq];          // broadcast, conflict-free
            ull w01 = (ull)wv.x;
            ull w23 = (ull)wv.y;
            ull cd;
            cd = pack2(c4.x, c4.x);
            p[0] = ffma2(cd, w01, p[0]);
            p[1] = ffma2(cd, w23, p[1]);
            cd = pack2(c4.y, c4.y);
            p[2] = ffma2(cd, w01, p[2]);
            p[3] = ffma2(cd, w23, p[3]);
            cd = pack2(c4.z, c4.z);
            p[4] = ffma2(cd, w01, p[4]);
            p[5] = ffma2(cd, w23, p[5]);
            cd = pack2(c4.w, c4.w);
            p[6] = ffma2(cd, w01, p[6]);
            p[7] = ffma2(cd, w23, p[7]);
        }
        Wv += (size_t)NJ * 32;

        #pragma unroll
        for (int r = 0; r < 4; r++) {
            float h = h_sm[(k - k0) * 32 + m0 + r];
            ull hd = pack2(h, h);
            acc[2 * r]     = ffma2(hd, p[2 * r],     acc[2 * r]);
            acc[2 * r + 1] = ffma2(hd, p[2 * r + 1], acc[2 * r + 1]);
        }
    }

    float4* out4 = reinterpret_cast<float4*>(g_tp);
    #pragma unroll
    for (int r = 0; r < 4; r++) {
        float4 o;
        unpack2(acc[2 * r],     o.x, o.y);
        unpack2(acc[2 * r + 1], o.z, o.w);
        out4[((size_t)split * N + base + m0 + r) * 32 + lw] = o;
    }
}

// ---------------------------------------------------------------------------
// Kernel 4: epilogue — sum splits, LN(128), silu(@om_w1), @om_w2 + b.
// 4 rows per 128-thread block (one row per warp in phase A/C).
// ---------------------------------------------------------------------------
__global__ __launch_bounds__(128) void out_kernel(const float* __restrict__ lng,
                                                  const float* __restrict__ lnb,
                                                  const float* __restrict__ w1,
                                                  const float* __restrict__ w2,
                                                  const float* __restrict__ b2,
                                                  float* __restrict__ out,
                                                  int N) {
    __shared__ float ln_sm[4][128];
    __shared__ float part_sm[4][128];
    int tid  = threadIdx.x;
    int lane = tid & 31;
    int warp = tid >> 5;
    int rowbase = blockIdx.x * 4;

    // Phase A: sum k-splits + LayerNorm; one row per warp
    {
        int g = rowbase + warp;
        float v[4];
        #pragma unroll
        for (int t = 0; t < 4; t++) {
            int i = lane + 32 * t;
            float s = 0.0f;
            #pragma unroll
            for (int sp = 0; sp < KSPLIT; sp++)
                s += g_tp[((size_t)sp * N + g) * 128 + i];
            v[t] = s;
        }
        float s = v[0] + v[1] + v[2] + v[3];
        #pragma unroll
        for (int o = 16; o; o >>= 1) s += __shfl_xor_sync(0xffffffffu, s, o);
        float mu = s * (1.0f / 128.0f);
        float ss = 0.0f;
        #pragma unroll
        for (int t = 0; t < 4; t++) { float d = v[t] - mu; ss += d * d; }
        #pragma unroll
        for (int o = 16; o; o >>= 1) ss += __shfl_xor_sync(0xffffffffu, ss, o);
        float rstd = rsqrtf(ss * (1.0f / 128.0f) + LN_EPS);
        #pragma unroll
        for (int t = 0; t < 4; t++) {
            int i = lane + 32 * t;
            ln_sm[warp][i] = (v[t] - mu) * rstd * lng[i] + lnb[i];
        }
    }
    __syncthreads();

    // Phase B: hidden = ln @ om_w1; thread owns j-quad tid*4..tid*4+3, 4 rows
    float y[4][4];
    #pragma unroll
    for (int r = 0; r < 4; r++)
        #pragma unroll
        for (int q = 0; q < 4; q++) y[r][q] = 0.0f;

    const float4* w1v = reinterpret_cast<const float4*>(w1);
    #pragma unroll 8
    for (int i = 0; i < 128; i++) {
        float4 wv = w1v[i * 128 + tid];
        #pragma unroll
        for (int r = 0; r < 4; r++) {
            float l = ln_sm[r][i];
            y[r][0] += l * wv.x;
            y[r][1] += l * wv.y;
            y[r][2] += l * wv.z;
            y[r][3] += l * wv.w;
        }
    }

    // Phase C: silu + dot with om_w2
    float4 w2v = reinterpret_cast<const float4*>(w2)[tid];
    #pragma unroll
    for (int r = 0; r < 4; r++) {
        float s = silu_f(y[r][0]) * w2v.x + silu_f(y[r][1]) * w2v.y +
                  silu_f(y[r][2]) * w2v.z + silu_f(y[r][3]) * w2v.w;
        part_sm[r][tid] = s;
    }
    __syncthreads();

    // Warp r reduces row r
    {
        float s = part_sm[warp][lane] + part_sm[warp][lane + 32] +
                  part_sm[warp][lane + 64] + part_sm[warp][lane + 96];
        #pragma unroll
        for (int o = 16; o; o >>= 1) s += __shfl_xor_sync(0xffffffffu, s, o);
        if (lane == 0) out[rowbase + warp] = s + b2[0];
    }
}

// ---------------------------------------------------------------------------
extern "C" void kernel_launch(void* const* d_in, const int* in_sizes, int n_in,
                              void* d_out, int out_size) {
    const float* x        = (const float*)d_in[0];
    const float* we_ln_g  = (const float*)d_in[1];
    const float* we_ln_b  = (const float*)d_in[2];
    const float* we_w1    = (const float*)d_in[3];
    const float* we_w2    = (const float*)d_in[4];
    const float* we_b2    = (const float*)d_in[5];
    const float* om_ln_g  = (const float*)d_in[6];
    const float* om_ln_b  = (const float*)d_in[7];
    const float* om_w1    = (const float*)d_in[8];
    const float* om_w2    = (const float*)d_in[9];
    const float* om_b2    = (const float*)d_in[10];

    int N = in_sizes[0] / 64;
    if (N > MAXN) N = MAXN;

    const int total = NK * NJ * NW;
    repack_kernel<<<(total + 255) / 256, 256>>>(we_w2, we_b2);
    prep_kernel<<<(N + 7) / 8, 256>>>(x, we_ln_g, we_ln_b, we_w1, N);
    tp_kernel<<<dim3(N / 32, KSPLIT), 256>>>(N);
    out_kernel<<<N / 4, 128>>>(om_ln_g, om_ln_b, om_w1, om_w2, om_b2,
                               (float*)d_out, N);
}

// round 6
// speedup vs baseline: 2.7458x; 2.7458x over previous
#include <cuda_runtime.h>
#include <cuda_bf16.h>

// ---------------------------------------------------------------------------
// WeightedTP via warp-level mma.sync (HMMA, plain sm_103-compatible):
//   tp = A[2048 x 65*272] @ Wsym[65*272 x 128],  A[n,(k,j)] = h[n,k]*c[n,j]
// bf16 hi/lo 3-term split (AhBh + AhBl + AlBh), fp32 accumulate.
// B pre-packed in mma m16n8k16 B-fragment layout (hi+lo in one uint4/lane).
// ---------------------------------------------------------------------------

#define MAXN 2048
#define NK 65            // 64 hidden + bias row (h=1)
#define NJ 272           // 17 chunks of 16
#define NJC 17
#define KSPLIT 9

#define PATH_COEFF 0.04419417382415922f
#define CG110      0.57735026918962576f
#define LN_EPS     1e-5f

__device__ float g_hT[64 * MAXN];                    // [k][n]
__device__ float g_c[MAXN * NJ];                     // [n][j]
__device__ float g_wsym[(size_t)NK * NJ * 128];      // [k][j][w]
__device__ uint4 g_bf[(size_t)NK * NJC * 16 * 32];   // B frags [k][jc][wt][lane]
__device__ float4 g_cf[(size_t)(MAXN/16) * NJC * 32 * 2]; // c frags [mt][jc][lane][2]
__device__ float g_tp[(size_t)KSPLIT * MAXN * 128];

__device__ __forceinline__ float silu_f(float v) { return v / (1.0f + __expf(-v)); }

// split fp32 pair into bf16x2 hi + bf16x2 lo (a0 -> low half)
__device__ __forceinline__ void split2(float a0, float a1, unsigned& hi, unsigned& lo) {
    unsigned h;
    asm("cvt.rn.bf16x2.f32 %0, %1, %2;" : "=r"(h) : "f"(a1), "f"(a0));
    float h0 = __uint_as_float(h << 16);
    float h1 = __uint_as_float(h & 0xFFFF0000u);
    float r0 = a0 - h0, r1 = a1 - h1;
    asm("cvt.rn.bf16x2.f32 %0, %1, %2;" : "=r"(lo) : "f"(r1), "f"(r0));
    hi = h;
}

__device__ __forceinline__ void mma16816(float* d, const unsigned* a,
                                         unsigned b0, unsigned b1) {
    asm volatile(
        "mma.sync.aligned.m16n8k16.row.col.f32.bf16.bf16.f32 "
        "{%0,%1,%2,%3}, {%4,%5,%6,%7}, {%8,%9}, {%0,%1,%2,%3};"
        : "+f"(d[0]), "+f"(d[1]), "+f"(d[2]), "+f"(d[3])
        : "r"(a[0]), "r"(a[1]), "r"(a[2]), "r"(a[3]), "r"(b0), "r"(b1));
}

// ---------------------------------------------------------------------------
// Kernel 1a: symmetrized Wsym[k][j][w] (fp32), coalesced.
// ---------------------------------------------------------------------------
__global__ void repack_kernel(const float* __restrict__ w2,
                              const float* __restrict__ b2) {
    int idx = blockIdx.x * blockDim.x + threadIdx.x;
    const int total = NK * NJ * 128;
    if (idx >= total) return;
    int w    = idx & 127;
    int rest = idx >> 7;
    int j    = rest % NJ;
    int k    = rest / NJ;
    int p = j / 136, q = j % 136, u = 0;
    while (q >= 16 - u) { q -= 16 - u; u++; }
    int v = u + q;
    const float* src = (k < 64) ? (w2 + (size_t)k * 65536) : b2;
    float val = src[((p * 256 + u * 16 + v) << 7) + w];
    if (u != v) val += src[((p * 256 + v * 16 + u) << 7) + w];
    g_wsym[idx] = val;
}

// ---------------------------------------------------------------------------
// Kernel 1b: pack Wsym into mma B-fragment layout, bf16 hi/lo.
// One thread per output uint4: (k, jc, wt, lane).
// lane: w = wt*8 + (lane>>2); j0 = jc*16 + (lane&3)*2; vals j0,j0+1,j0+8,j0+9.
// ---------------------------------------------------------------------------
__global__ void frag_kernel() {
    int idx = blockIdx.x * blockDim.x + threadIdx.x;
    const int total = NK * NJC * 16 * 32;
    if (idx >= total) return;
    int lane = idx & 31;
    int wt   = (idx >> 5) & 15;
    int rest = idx >> 9;
    int jc   = rest % NJC;
    int k    = rest / NJC;
    int w  = wt * 8 + (lane >> 2);
    int j0 = jc * 16 + (lane & 3) * 2;
    const float* Wp = g_wsym + ((size_t)k * NJ + j0) * 128 + w;
    float v0 = Wp[0], v1 = Wp[128], v2 = Wp[8 * 128], v3 = Wp[9 * 128];
    uint4 o;
    split2(v0, v1, o.x, o.z);
    split2(v2, v3, o.y, o.w);
    g_bf[idx] = o;
}

// ---------------------------------------------------------------------------
// Kernel 2: per-row prep — h (transposed [k][n]), c ([n][j]).
// ---------------------------------------------------------------------------
__global__ void prep_kernel(const float* __restrict__ x,
                            const float* __restrict__ lng,
                            const float* __restrict__ lnb,
                            const float* __restrict__ w1, int N) {
    __shared__ float xs[8][64];
    __shared__ float lns[8][16];
    int warp = threadIdx.x >> 5;
    int lane = threadIdx.x & 31;
    int n = blockIdx.x * 8 + warp;
    if (n >= N) return;

    xs[warp][lane]      = x[(size_t)n * 64 + lane];
    xs[warp][lane + 32] = x[(size_t)n * 64 + 32 + lane];
    __syncwarp();

    float f = (lane < 16) ? xs[warp][lane] : 0.0f;
    float s = f;
    #pragma unroll
    for (int o = 16; o; o >>= 1) s += __shfl_xor_sync(0xffffffffu, s, o);
    float mu = s * (1.0f / 16.0f);
    float d = (lane < 16) ? (f - mu) : 0.0f;
    float ss = d * d;
    #pragma unroll
    for (int o = 16; o; o >>= 1) ss += __shfl_xor_sync(0xffffffffu, ss, o);
    float rstd = rsqrtf(ss * (1.0f / 16.0f) + LN_EPS);
    if (lane < 16) lns[warp][lane] = d * rstd * lng[lane] + lnb[lane];
    __syncwarp();

    #pragma unroll
    for (int t = 0; t < 2; t++) {
        int j = lane + 32 * t;
        float acc = 0.0f;
        #pragma unroll
        for (int i = 0; i < 16; i++) acc += lns[warp][i] * w1[i * 64 + j];
        g_hT[(size_t)j * MAXN + n] = silu_f(acc);
    }

    for (int t = lane; t < NJ; t += 32) {
        int p = t / 136, q = t % 136, u = 0;
        while (q >= 16 - u) { q -= 16 - u; u++; }
        int v = u + q;
        float val;
        if (p == 0) {
            val = PATH_COEFF * xs[warp][u] * xs[warp][v];
        } else {
            const float* a = &xs[warp][16 + u * 3];
            const float* b = &xs[warp][16 + v * 3];
            val = PATH_COEFF * CG110 * (a[0] * b[0] + a[1] * b[1] + a[2] * b[2]);
        }
        g_c[(size_t)n * NJ + t] = val;
    }
}

// ---------------------------------------------------------------------------
// Kernel 2b: pack c into A-fragment-ordered fp32 quads.
// Thread per (mt, jc, lane): f4#0 = {c(ra,j0),c(ra,j0+1),c(ra+8,j0),c(ra+8,j0+1)}
//                            f4#1 = same at j0+8,j0+9.
// ---------------------------------------------------------------------------
__global__ void cfrag_kernel(int N) {
    int idx = blockIdx.x * blockDim.x + threadIdx.x;
    int total = (N / 16) * NJC * 32;
    if (idx >= total) return;
    int lane = idx & 31;
    int jc   = (idx >> 5) % NJC;
    int mt   = idx / (32 * NJC);
    int ra = lane >> 2;
    int j0 = jc * 16 + (lane & 3) * 2;
    const float* c0 = g_c + (size_t)(mt * 16 + ra) * NJ;
    const float* c8 = c0 + 8 * NJ;
    float4 f0, f1;
    f0.x = c0[j0];     f0.y = c0[j0 + 1]; f0.z = c8[j0];     f0.w = c8[j0 + 1];
    f1.x = c0[j0 + 8]; f1.y = c0[j0 + 9]; f1.z = c8[j0 + 8]; f1.w = c8[j0 + 9];
    size_t o = ((size_t)(mt * NJC + jc) * 32 + lane) * 2;
    g_cf[o] = f0;
    g_cf[o + 1] = f1;
}

// ---------------------------------------------------------------------------
// Kernel 3: HMMA contraction. Grid (N/128, KSPLIT), 256 threads (8 warps).
// Warp = (mw = wid>>1: 32 rows, nh = wid&1: 64 w-cols). acc[2 mtl][8 wt][4].
// ---------------------------------------------------------------------------
__global__ __launch_bounds__(256, 1) void tp_kernel(int N) {
    __shared__ float h_sm[8 * 128];
    int tid = threadIdx.x;
    int warp = tid >> 5;
    int lane = tid & 31;
    int mblk = blockIdx.x;
    int base = mblk * 128;
    int split = blockIdx.y;
    int k0 = (split * NK) / KSPLIT;
    int k1 = ((split + 1) * NK) / KSPLIT;
    int kc = k1 - k0;

    for (int s = tid; s < kc * 128; s += 256) {
        int k = k0 + (s >> 7);
        h_sm[s] = (k == 64) ? 1.0f : g_hT[(size_t)k * MAXN + base + (s & 127)];
    }
    __syncthreads();

    int mw = warp >> 1;
    int nh = warp & 1;
    int ra = lane >> 2;
    int qb = lane & 3;

    float acc[2][8][4];
    #pragma unroll
    for (int a = 0; a < 2; a++)
        #pragma unroll
        for (int b = 0; b < 8; b++)
            #pragma unroll
            for (int cdx = 0; cdx < 4; cdx++) acc[a][b][cdx] = 0.0f;

    for (int jc = 0; jc < NJC; jc++) {
        float4 cf[2][2];
        #pragma unroll
        for (int mtl = 0; mtl < 2; mtl++) {
            int mt = mblk * 8 + mw * 2 + mtl;
            size_t o = ((size_t)(mt * NJC + jc) * 32 + lane) * 2;
            cf[mtl][0] = g_cf[o];
            cf[mtl][1] = g_cf[o + 1];
        }
        for (int kk = 0; kk < kc; kk++) {
            unsigned ah[2][4], al[2][4];
            #pragma unroll
            for (int mtl = 0; mtl < 2; mtl++) {
                int r0 = mw * 32 + mtl * 16 + ra;
                float h0 = h_sm[kk * 128 + r0];
                float h1 = h_sm[kk * 128 + r0 + 8];
                split2(h0 * cf[mtl][0].x, h0 * cf[mtl][0].y, ah[mtl][0], al[mtl][0]);
                split2(h1 * cf[mtl][0].z, h1 * cf[mtl][0].w, ah[mtl][1], al[mtl][1]);
                split2(h0 * cf[mtl][1].x, h0 * cf[mtl][1].y, ah[mtl][2], al[mtl][2]);
                split2(h1 * cf[mtl][1].z, h1 * cf[mtl][1].w, ah[mtl][3], al[mtl][3]);
            }
            const uint4* bp = g_bf + (((size_t)(k0 + kk) * NJC + jc) * 16 + nh * 8) * 32 + lane;
            #pragma unroll
            for (int wt = 0; wt < 8; wt++) {
                uint4 bb = bp[(size_t)wt * 32];
                mma16816(acc[0][wt], ah[0], bb.x, bb.y);   // Ah*Bh
                mma16816(acc[1][wt], ah[1], bb.x, bb.y);
                mma16816(acc[0][wt], ah[0], bb.z, bb.w);   // Ah*Bl
                mma16816(acc[1][wt], ah[1], bb.z, bb.w);
                mma16816(acc[0][wt], al[0], bb.x, bb.y);   // Al*Bh
                mma16816(acc[1][wt], al[1], bb.x, bb.y);
            }
        }
    }

    // D layout: d0,d1 = (row ra, col 2qb, 2qb+1); d2,d3 = row ra+8.
    #pragma unroll
    for (int mtl = 0; mtl < 2; mtl++) {
        int r0 = base + mw * 32 + mtl * 16 + ra;
        #pragma unroll
        for (int wt = 0; wt < 8; wt++) {
            int col = nh * 64 + wt * 8 + 2 * qb;
            float2* p0 = reinterpret_cast<float2*>(
                g_tp + ((size_t)split * N + r0) * 128 + col);
            float2* p1 = reinterpret_cast<float2*>(
                g_tp + ((size_t)split * N + r0 + 8) * 128 + col);
            *p0 = make_float2(acc[mtl][wt][0], acc[mtl][wt][1]);
            *p1 = make_float2(acc[mtl][wt][2], acc[mtl][wt][3]);
        }
    }
}

// ---------------------------------------------------------------------------
// Kernel 4: epilogue — sum splits, LN(128), silu(@om_w1), @om_w2 + b.
// 8 rows per 256-thread block; om_w1 i-dim split across 2 thread-halves.
// ---------------------------------------------------------------------------
__global__ __launch_bounds__(256) void out_kernel(const float* __restrict__ lng,
                                                  const float* __restrict__ lnb,
                                                  const float* __restrict__ w1,
                                                  const float* __restrict__ w2,
                                                  const float* __restrict__ bias2,
                                                  float* __restrict__ out, int N) {
    __shared__ float ln_sm[8][128];
    __shared__ float y_sm[8][512];
    __shared__ float part_sm[8][128];
    int tid = threadIdx.x, lane = tid & 31, warp = tid >> 5;
    int rowbase = blockIdx.x * 8;

    // Phase A: one row per warp — sum 9 splits + LayerNorm
    {
        int g = rowbase + warp;
        float v[4];
        #pragma unroll
        for (int t = 0; t < 4; t++) {
            int i = lane + 32 * t;
            float s = 0.0f;
            #pragma unroll
            for (int sp = 0; sp < KSPLIT; sp++)
                s += g_tp[((size_t)sp * N + g) * 128 + i];
            v[t] = s;
        }
        float s = v[0] + v[1] + v[2] + v[3];
        #pragma unroll
        for (int o = 16; o; o >>= 1) s += __shfl_xor_sync(0xffffffffu, s, o);
        float mu = s * (1.0f / 128.0f);
        float ss = 0.0f;
        #pragma unroll
        for (int t = 0; t < 4; t++) { float d = v[t] - mu; ss += d * d; }
        #pragma unroll
        for (int o = 16; o; o >>= 1) ss += __shfl_xor_sync(0xffffffffu, ss, o);
        float rstd = rsqrtf(ss * (1.0f / 128.0f) + LN_EPS);
        #pragma unroll
        for (int t = 0; t < 4; t++) {
            int i = lane + 32 * t;
            ln_sm[warp][i] = (v[t] - mu) * rstd * lng[i] + lnb[i];
        }
    }
    __syncthreads();

    // Phase B: y[r][q4] += ln[r][i] * w1[i][q4], i split across 2 halves
    int q = tid & 127, hf = tid >> 7;
    float y[8][4];
    #pragma unroll
    for (int r = 0; r < 8; r++)
        #pragma unroll
        for (int cdx = 0; cdx < 4; cdx++) y[r][cdx] = 0.0f;

    const float4* w1v = reinterpret_cast<const float4*>(w1);
    #pragma unroll 8
    for (int ii = 0; ii < 64; ii++) {
        int i = hf * 64 + ii;
        float4 wv = w1v[i * 128 + q];
        #pragma unroll
        for (int r = 0; r < 8; r++) {
            float l = ln_sm[r][i];
            y[r][0] += l * wv.x;
            y[r][1] += l * wv.y;
            y[r][2] += l * wv.z;
            y[r][3] += l * wv.w;
        }
    }
    if (hf == 1) {
        #pragma unroll
        for (int r = 0; r < 8; r++) {
            y_sm[r][q * 4]     = y[r][0];
            y_sm[r][q * 4 + 1] = y[r][1];
            y_sm[r][q * 4 + 2] = y[r][2];
            y_sm[r][q * 4 + 3] = y[r][3];
        }
    }
    __syncthreads();

    if (hf == 0) {
        float4 w2v = reinterpret_cast<const float4*>(w2)[q];
        #pragma unroll
        for (int r = 0; r < 8; r++) {
            float a0 = y[r][0] + y_sm[r][q * 4];
            float a1 = y[r][1] + y_sm[r][q * 4 + 1];
            float a2 = y[r][2] + y_sm[r][q * 4 + 2];
            float a3 = y[r][3] + y_sm[r][q * 4 + 3];
            part_sm[r][q] = silu_f(a0) * w2v.x + silu_f(a1) * w2v.y +
                            silu_f(a2) * w2v.z + silu_f(a3) * w2v.w;
        }
    }
    __syncthreads();

    // Warp w reduces row w
    {
        float s = part_sm[warp][lane] + part_sm[warp][lane + 32] +
                  part_sm[warp][lane + 64] + part_sm[warp][lane + 96];
        #pragma unroll
        for (int o = 16; o; o >>= 1) s += __shfl_xor_sync(0xffffffffu, s, o);
        if (lane == 0) out[rowbase + warp] = s + bias2[0];
    }
}

// ---------------------------------------------------------------------------
extern "C" void kernel_launch(void* const* d_in, const int* in_sizes, int n_in,
                              void* d_out, int out_size) {
    const float* x        = (const float*)d_in[0];
    const float* we_ln_g  = (const float*)d_in[1];
    const float* we_ln_b  = (const float*)d_in[2];
    const float* we_w1    = (const float*)d_in[3];
    const float* we_w2    = (const float*)d_in[4];
    const float* we_b2    = (const float*)d_in[5];
    const float* om_ln_g  = (const float*)d_in[6];
    const float* om_ln_b  = (const float*)d_in[7];
    const float* om_w1    = (const float*)d_in[8];
    const float* om_w2    = (const float*)d_in[9];
    const float* om_b2    = (const float*)d_in[10];

    int N = in_sizes[0] / 64;
    if (N > MAXN) N = MAXN;

    const int totalW = NK * NJ * 128;
    const int totalF = NK * NJC * 16 * 32;
    const int totalC = (N / 16) * NJC * 32;

    repack_kernel<<<(totalW + 255) / 256, 256>>>(we_w2, we_b2);
    frag_kernel<<<(totalF + 255) / 256, 256>>>();
    prep_kernel<<<(N + 7) / 8, 256>>>(x, we_ln_g, we_ln_b, we_w1, N);
    cfrag_kernel<<<(totalC + 255) / 256, 256>>>(N);
    tp_kernel<<<dim3(N / 128, KSPLIT), 256>>>(N);
    out_kernel<<<N / 8, 256>>>(om_ln_g, om_ln_b, om_w1, om_w2, om_b2,
                               (float*)d_out, N);
}